// round 15
// baseline (speedup 1.0000x reference)
#include <cuda_runtime.h>
#include <cuda_fp16.h>
#include <math.h>
#include <stdint.h>

#define BB    4
#define NQ    4096
#define CC    512
#define HEADS 8
#define DH    64
#define NKV   256
#define KCONV 8192
#define CSPLIT 16

// ---------------------------------------------------------------------------
// Scratch
// ---------------------------------------------------------------------------
__device__ __half g_xh[BB * NQ * CC];
__device__ __half g_qh[BB * NQ * CC];
__device__ __half g_kh[BB * NKV * CC];
__device__ __half g_vh[BB * NKV * CC];
__device__ __half g_attnh[BB * NQ * CC];
__device__ __half g_xrh[BB * NKV * CC];
__device__ __half g_xr_parth[CSPLIT * BB * NKV * CC];   // fp16 conv partials
__device__ __half g_wqh[CC * CC];
__device__ __half g_wkh[CC * CC];
__device__ __half g_wvh[CC * CC];
__device__ __half g_wph[CC * CC];
__device__ __half g_wsrh[(size_t)KCONV * CC];

// ---------------------------------------------------------------------------
// helpers
// ---------------------------------------------------------------------------
__device__ __forceinline__ void mma_f16(float* c,
    uint32_t a0, uint32_t a1, uint32_t a2, uint32_t a3, uint32_t b0, uint32_t b1)
{
    asm volatile(
        "mma.sync.aligned.m16n8k16.row.col.f32.f16.f16.f32 "
        "{%0,%1,%2,%3},{%4,%5,%6,%7},{%8,%9},{%0,%1,%2,%3};"
        : "+f"(c[0]), "+f"(c[1]), "+f"(c[2]), "+f"(c[3])
        : "r"(a0), "r"(a1), "r"(a2), "r"(a3), "r"(b0), "r"(b1));
}

__device__ __forceinline__ void ldsm_x4(uint32_t addr,
    uint32_t& r0, uint32_t& r1, uint32_t& r2, uint32_t& r3)
{
    asm volatile("ldmatrix.sync.aligned.m8n8.x4.shared.b16 {%0,%1,%2,%3}, [%4];"
        : "=r"(r0), "=r"(r1), "=r"(r2), "=r"(r3) : "r"(addr));
}

__device__ __forceinline__ void ldsm_x4_t(uint32_t addr,
    uint32_t& r0, uint32_t& r1, uint32_t& r2, uint32_t& r3)
{
    asm volatile("ldmatrix.sync.aligned.m8n8.x4.trans.shared.b16 {%0,%1,%2,%3}, [%4];"
        : "=r"(r0), "=r"(r1), "=r"(r2), "=r"(r3) : "r"(addr));
}

__device__ __forceinline__ uint32_t smem_u32(const void* p) {
    uint32_t a;
    asm("{ .reg .u64 t; cvta.to.shared.u64 t, %1; cvt.u32.u64 %0, t; }" : "=r"(a) : "l"(p));
    return a;
}

#define CP16(dst, src) \
    asm volatile("cp.async.cg.shared.global [%0], [%1], 16;" :: "r"(dst), "l"(src))
#define CPCOMMIT() asm volatile("cp.async.commit_group;" ::: "memory")

// ---------------------------------------------------------------------------
// fp16 GEMM core v2: 128x128 tile, K-step 64, 3-stage cp.async.
// 512 threads = 16 warps, warp grid 4m x 4n, warp tile 32x32 (acc = 32 regs).
// Fragment load patterns identical to the proven R13 core.
// ---------------------------------------------------------------------------
#define NSTAGE 3
#define AP   72
#define BP2  136
#define A_BYTES (128 * AP * 2)
#define B_OFF   A_BYTES
#define STAGE_BYTES (A_BYTES + 64 * BP2 * 2)
#define GEMM_SMEM (NSTAGE * STAGE_BYTES + 512)

template<bool OUTHALF, bool BIAS>
__device__ __forceinline__ void gemm_core(
    const __half* __restrict__ arow,   // per-thread A row base (row = tid>>2)
    const __half* __restrict__ Bk,
    const float* __restrict__ bias,
    void* __restrict__ Cp, int ldc,
    int nkt, int bm, int bn)
{
    extern __shared__ __align__(16) char smem[];
    float* sbias = (float*)(smem + NSTAGE * STAGE_BYTES);

    const int tid = threadIdx.x;
    const int w = tid >> 5, l = tid & 31;
    const int g = l >> 2, t = l & 3;
    const int wm = (w >> 2) * 32;
    const int wn = (w & 3) * 32;

    if (BIAS && tid < 128) sbias[tid] = bias[bn + tid];

    // A staging: row = tid>>2 (0..127), thread covers halves [segA, segA+16)
    const int segA = (tid & 3) * 16;
    // B staging: bK = tid>>3 (0..63), thread covers halves [bN, bN+16)
    const int bK = tid >> 3;
    const int bN = (tid & 7) * 16;
    const uint32_t sb = smem_u32(smem);
    const uint32_t a_tb = (uint32_t)(((wm + (l & 15)) * AP + ((l >> 4) << 3)) * 2);
    const uint32_t b_tb = (uint32_t)(((l & 15) * BP2 + wn + ((l >> 4) << 3)) * 2);

    float acc[2][4][4];
#pragma unroll
    for (int mi = 0; mi < 2; ++mi)
#pragma unroll
        for (int ni = 0; ni < 4; ++ni)
#pragma unroll
            for (int e = 0; e < 4; ++e) acc[mi][ni][e] = 0.f;

#define ISSUE(ktArg, stArg) { \
    const uint32_t _ab = sb + (stArg) * STAGE_BYTES; \
    const __half* _ap = arow + (ktArg) * 64 + segA; \
    const uint32_t _ad = _ab + (uint32_t)((tid >> 2) * AP + segA) * 2; \
    CP16(_ad, _ap); CP16(_ad + 16, _ap + 8); \
    const uint32_t _bb = _ab + B_OFF; \
    const __half* _bp = Bk + (size_t)((ktArg) * 64 + bK) * 512 + bn + bN; \
    const uint32_t _bd = _bb + (uint32_t)(bK * BP2 + bN) * 2; \
    CP16(_bd, _bp); CP16(_bd + 16, _bp + 8); }

    ISSUE(0, 0); CPCOMMIT();
    if (nkt > 1) ISSUE(1, 1);
    CPCOMMIT();

    int buf = 0, nxt = 2;
    for (int kt = 0; kt < nkt; ++kt) {
        asm volatile("cp.async.wait_group 1;" ::: "memory");
        __syncthreads();
        if (kt + 2 < nkt) ISSUE(kt + 2, nxt);
        CPCOMMIT();

        const uint32_t abase = sb + buf * STAGE_BYTES;
        const uint32_t bbase = abase + B_OFF;

#pragma unroll
        for (int kk = 0; kk < 4; ++kk) {
            uint32_t a[2][4];
#pragma unroll
            for (int mi = 0; mi < 2; ++mi)
                ldsm_x4(abase + a_tb + (uint32_t)(mi * 16 * AP * 2 + kk * 32),
                        a[mi][0], a[mi][1], a[mi][2], a[mi][3]);
            uint32_t b[4][2];
            {
                const uint32_t bk0 = bbase + b_tb + (uint32_t)(kk * 16 * BP2 * 2);
                ldsm_x4_t(bk0,      b[0][0], b[0][1], b[1][0], b[1][1]);
                ldsm_x4_t(bk0 + 32, b[2][0], b[2][1], b[3][0], b[3][1]);
            }
#pragma unroll
            for (int ni = 0; ni < 4; ++ni)
#pragma unroll
                for (int mi = 0; mi < 2; ++mi)
                    mma_f16(acc[mi][ni], a[mi][0], a[mi][1], a[mi][2], a[mi][3],
                            b[ni][0], b[ni][1]);
        }
        buf = (buf == 2) ? 0 : buf + 1;
        nxt = (nxt == 2) ? 0 : nxt + 1;
    }
#undef ISSUE

    __syncthreads();

#pragma unroll
    for (int mi = 0; mi < 2; ++mi) {
        const int r0 = bm + wm + mi * 16 + g;
#pragma unroll
        for (int ni = 0; ni < 4; ++ni) {
            const int cl = wn + ni * 8 + 2 * t;
            const int cn = bn + cl;
            float f0 = acc[mi][ni][0], f1 = acc[mi][ni][1];
            float f2 = acc[mi][ni][2], f3 = acc[mi][ni][3];
            if (BIAS) {
                const float b0 = sbias[cl], b1 = sbias[cl + 1];
                f0 += b0; f1 += b1; f2 += b0; f3 += b1;
            }
            if (OUTHALF) {
                __half* C = (__half*)Cp;
                *(__half2*)&C[(size_t)r0 * ldc + cn] = __floats2half2_rn(f0, f1);
                *(__half2*)&C[(size_t)(r0 + 8) * ldc + cn] = __floats2half2_rn(f2, f3);
            } else {
                float* C = (float*)Cp;
                *(float2*)&C[(size_t)r0 * ldc + cn] = make_float2(f0, f1);
                *(float2*)&C[(size_t)(r0 + 8) * ldc + cn] = make_float2(f2, f3);
            }
        }
    }
}

// ---------------------------------------------------------------------------
// conv-only kernel: grid 512, 512 threads. fp16 partials.
// ---------------------------------------------------------------------------
__global__ void __launch_bounds__(512, 2) conv_tc()
{
    const int c = blockIdx.x;
    const int r = threadIdx.x >> 2;
    const int z = c >> 5, tl = c & 31;
    const int bm = (tl >> 2) * 128, bn = (tl & 3) * 128;
    const int gr = bm + r;
    const int pix = (gr >> 8) * 4096 + (((gr >> 4) & 15) << 8) + ((gr & 15) << 2);
    const int off = ((z >> 2) << 6) | (z & 3);
    const __half* arow = g_xh + (size_t)(pix + off) * 512;
    gemm_core<true, false>(arow, g_wsrh + (size_t)z * 512 * 512, nullptr,
                           g_xr_parth + (size_t)z * (BB * NKV * CC), 512, 8, bm, bn);
}

// ---------------------------------------------------------------------------
// merged qproj + K + V kernel: grid 576, 512 threads
// ---------------------------------------------------------------------------
__global__ void __launch_bounds__(512, 2) qkv_tc(const float* __restrict__ bq,
                                                 const float* __restrict__ bk,
                                                 const float* __restrict__ bv)
{
    const int bid = blockIdx.x;
    const int r = threadIdx.x >> 2;
    if (bid < 512) {
        const int bm = (bid >> 2) * 128, bn = (bid & 3) * 128;
        const __half* arow = g_xh + (size_t)(bm + r) * 512;
        gemm_core<true, true>(arow, g_wqh, bq, g_qh, 512, 8, bm, bn);
    } else {
        const int tl = bid - 512;
        const int sel = tl >> 5;
        const int tt = tl & 31;
        const int bm = (tt >> 2) * 128, bn = (tt & 3) * 128;
        const __half* arow = g_xrh + (size_t)(bm + r) * 512;
        if (sel == 0)
            gemm_core<true, true>(arow, g_wkh, bk, g_kh, 512, 8, bm, bn);
        else
            gemm_core<true, true>(arow, g_wvh, bv, g_vh, 512, 8, bm, bn);
    }
}

__global__ void __launch_bounds__(512, 2) outproj_tc(const float* __restrict__ bp,
                                                     float* __restrict__ out)
{
    const int bid = blockIdx.x;
    const int bm = (bid >> 2) * 128, bn = (bid & 3) * 128;
    const __half* arow = g_attnh + (size_t)(bm + (threadIdx.x >> 2)) * 512;
    gemm_core<false, true>(arow, g_wph, bp, out, 512, 8, bm, bn);
}

// ---------------------------------------------------------------------------
// Convert x + all weights to fp16
// ---------------------------------------------------------------------------
__global__ void convert_all(const float* __restrict__ x,
                            const float* __restrict__ wq,
                            const float* __restrict__ wk,
                            const float* __restrict__ wv,
                            const float* __restrict__ wp,
                            const float* __restrict__ w_sr)
{
    const size_t cid = (size_t)blockIdx.x * blockDim.x + threadIdx.x;
    const float* src;
    __half* dst;
    size_t loc;
    if (cid < 1048576)        { src = x;    dst = g_xh;  loc = cid; }
    else if (cid < 1081344)   { src = wq;   dst = g_wqh; loc = cid - 1048576; }
    else if (cid < 1114112)   { src = wk;   dst = g_wkh; loc = cid - 1081344; }
    else if (cid < 1146880)   { src = wv;   dst = g_wvh; loc = cid - 1114112; }
    else if (cid < 1179648)   { src = wp;   dst = g_wph; loc = cid - 1146880; }
    else                      { src = w_sr; dst = g_wsrh; loc = cid - 1179648; }
    const size_t i = loc * 8;
    float4 u = *(const float4*)&src[i];
    float4 v = *(const float4*)&src[i + 4];
    __half2 h0 = __floats2half2_rn(u.x, u.y);
    __half2 h1 = __floats2half2_rn(u.z, u.w);
    __half2 h2 = __floats2half2_rn(v.x, v.y);
    __half2 h3 = __floats2half2_rn(v.z, v.w);
    uint4 pk;
    pk.x = *(uint32_t*)&h0; pk.y = *(uint32_t*)&h1;
    pk.z = *(uint32_t*)&h2; pk.w = *(uint32_t*)&h3;
    *(uint4*)&dst[i] = pk;
}

// ---------------------------------------------------------------------------
// split-K reduce (fp16 partials) + bias + LayerNorm -> fp16
// ---------------------------------------------------------------------------
__global__ void ln_kernel(const float* __restrict__ bsr,
                          const float* __restrict__ gamma,
                          const float* __restrict__ beta)
{
    const int r = blockIdx.x;
    const int tid = threadIdx.x;
    float v[4];
    float s1 = 0.f, s2 = 0.f;
#pragma unroll
    for (int i = 0; i < 4; ++i) {
        const int c = tid + i * 128;
        const size_t off = (size_t)r * 512 + c;
        float tt = bsr[c];
#pragma unroll
        for (int p = 0; p < CSPLIT; ++p)
            tt += __half2float(g_xr_parth[(size_t)p * (BB * NKV * CC) + off]);
        v[i] = tt;
        s1 += tt;
        s2 += tt * tt;
    }
#pragma unroll
    for (int o = 16; o > 0; o >>= 1) {
        s1 += __shfl_xor_sync(0xffffffffu, s1, o);
        s2 += __shfl_xor_sync(0xffffffffu, s2, o);
    }
    __shared__ float red[8];
    const int warp = tid >> 5, lane = tid & 31;
    if (lane == 0) { red[warp] = s1; red[warp + 4] = s2; }
    __syncthreads();
    s1 = red[0] + red[1] + red[2] + red[3];
    s2 = red[4] + red[5] + red[6] + red[7];
    const float mu = s1 * (1.f / 512.f);
    const float var = s2 * (1.f / 512.f) - mu * mu;
    const float rstd = rsqrtf(var + 1e-5f);
#pragma unroll
    for (int i = 0; i < 4; ++i) {
        const int c = tid + i * 128;
        g_xrh[(size_t)r * 512 + c] = __float2half((v[i] - mu) * rstd * gamma[c] + beta[c]);
    }
}

// ---------------------------------------------------------------------------
// Attention v3 (byte-identical to passing R14)
// ---------------------------------------------------------------------------
#define QP 72
#define KP 72
#define VP 72
#define PP 280
#define ATT_K0 9216
#define ATT_V0 46080
#define ATT_RM 82944
#define ATT_RS 83968
#define ATT_SMEM 84992

__global__ void __launch_bounds__(256, 2) attn_kernel()
{
    extern __shared__ __align__(16) char smem[];
    __half* Ph = (__half*)smem;
    float* redmax = (float*)(smem + ATT_RM);
    float* redsum = (float*)(smem + ATT_RS);

    const int tid = threadIdx.x;
    const int w = tid >> 5, l = tid & 31;
    const int g = l >> 2, t = l & 3;
    const uint32_t sbA = smem_u32(smem);

    const int bh = blockIdx.y;
    const int b = bh >> 3, h = bh & 7;
    const int q0 = blockIdx.x * 64;
    const size_t qbase  = ((size_t)(b * NQ + q0)) * CC + h * DH;
    const size_t kvbase = ((size_t)(b * NKV)) * CC + h * DH;

#pragma unroll
    for (int i = 0; i < 2; ++i) {
        const int c = tid + i * 256;
        const int r = c >> 3, seg = (c & 7) * 8;
        CP16(sbA + (uint32_t)(r * QP + seg) * 2, &g_qh[qbase + (size_t)r * CC + seg]);
    }
#pragma unroll
    for (int i = 0; i < 8; ++i) {
        const int c = tid + i * 256;
        const int r = c >> 3, seg = (c & 7) * 8;
        CP16(sbA + ATT_K0 + (uint32_t)(r * KP + seg) * 2, &g_kh[kvbase + (size_t)r * CC + seg]);
    }
    CPCOMMIT();
#pragma unroll
    for (int i = 0; i < 8; ++i) {
        const int c = tid + i * 256;
        const int r = c >> 3, seg = (c & 7) * 8;
        CP16(sbA + ATT_V0 + (uint32_t)(r * VP + seg) * 2, &g_vh[kvbase + (size_t)r * CC + seg]);
    }
    CPCOMMIT();
    asm volatile("cp.async.wait_group 1;" ::: "memory");
    __syncthreads();

    const int wm = (w >> 2) * 32;
    const int wn = (w & 3) * 64;

    const uint32_t q_tb = sbA + (uint32_t)(((wm + (l & 15)) * QP + ((l >> 4) << 3)) * 2);
    const uint32_t k_tb = sbA + ATT_K0 + (uint32_t)(((wn + (l & 15)) * KP + ((l >> 4) << 3)) * 2);

    float accS[2][8][4];
#pragma unroll
    for (int mi = 0; mi < 2; ++mi)
#pragma unroll
        for (int ni = 0; ni < 8; ++ni)
#pragma unroll
            for (int e = 0; e < 4; ++e) accS[mi][ni][e] = 0.f;

#pragma unroll
    for (int kk = 0; kk < 4; ++kk) {
        uint32_t a[2][4];
#pragma unroll
        for (int mi = 0; mi < 2; ++mi)
            ldsm_x4(q_tb + (uint32_t)(mi * 16 * QP * 2 + kk * 32),
                    a[mi][0], a[mi][1], a[mi][2], a[mi][3]);
#pragma unroll
        for (int j = 0; j < 4; ++j) {
            uint32_t r0, r1, r2, r3;
            ldsm_x4(k_tb + (uint32_t)(j * 16 * KP * 2 + kk * 32), r0, r1, r2, r3);
#pragma unroll
            for (int mi = 0; mi < 2; ++mi) {
                mma_f16(accS[mi][2 * j],     a[mi][0], a[mi][1], a[mi][2], a[mi][3], r0, r2);
                mma_f16(accS[mi][2 * j + 1], a[mi][0], a[mi][1], a[mi][2], a[mi][3], r1, r3);
            }
        }
    }
#pragma unroll
    for (int mi = 0; mi < 2; ++mi)
#pragma unroll
        for (int ni = 0; ni < 8; ++ni)
#pragma unroll
            for (int e = 0; e < 4; ++e) accS[mi][ni][e] *= 0.125f;

#pragma unroll
    for (int mi = 0; mi < 2; ++mi) {
        float m0 = -1e30f, m1 = -1e30f;
#pragma unroll
        for (int ni = 0; ni < 8; ++ni) {
            m0 = fmaxf(m0, fmaxf(accS[mi][ni][0], accS[mi][ni][1]));
            m1 = fmaxf(m1, fmaxf(accS[mi][ni][2], accS[mi][ni][3]));
        }
        m0 = fmaxf(m0, __shfl_xor_sync(0xffffffffu, m0, 1));
        m0 = fmaxf(m0, __shfl_xor_sync(0xffffffffu, m0, 2));
        m1 = fmaxf(m1, __shfl_xor_sync(0xffffffffu, m1, 1));
        m1 = fmaxf(m1, __shfl_xor_sync(0xffffffffu, m1, 2));
        if (t == 0) {
            redmax[(w & 3) * 64 + wm + mi * 16 + g]     = m0;
            redmax[(w & 3) * 64 + wm + mi * 16 + g + 8] = m1;
        }
    }
    __syncthreads();

#pragma unroll
    for (int mi = 0; mi < 2; ++mi) {
        const int r0 = wm + mi * 16 + g;
        const float m0 = fmaxf(fmaxf(redmax[r0], redmax[64 + r0]),
                               fmaxf(redmax[128 + r0], redmax[192 + r0]));
        const float m1 = fmaxf(fmaxf(redmax[r0 + 8], redmax[64 + r0 + 8]),
                               fmaxf(redmax[128 + r0 + 8], redmax[192 + r0 + 8]));
        float s0 = 0.f, s1 = 0.f;
#pragma unroll
        for (int ni = 0; ni < 8; ++ni) {
            accS[mi][ni][0] = __expf(accS[mi][ni][0] - m0);
            accS[mi][ni][1] = __expf(accS[mi][ni][1] - m0);
            accS[mi][ni][2] = __expf(accS[mi][ni][2] - m1);
            accS[mi][ni][3] = __expf(accS[mi][ni][3] - m1);
            s0 += accS[mi][ni][0] + accS[mi][ni][1];
            s1 += accS[mi][ni][2] + accS[mi][ni][3];
        }
        s0 += __shfl_xor_sync(0xffffffffu, s0, 1);
        s0 += __shfl_xor_sync(0xffffffffu, s0, 2);
        s1 += __shfl_xor_sync(0xffffffffu, s1, 1);
        s1 += __shfl_xor_sync(0xffffffffu, s1, 2);
        if (t == 0) {
            redsum[(w & 3) * 64 + r0]     = s0;
            redsum[(w & 3) * 64 + r0 + 8] = s1;
        }
    }
    asm volatile("cp.async.wait_group 0;" ::: "memory");
    __syncthreads();

#pragma unroll
    for (int mi = 0; mi < 2; ++mi) {
        const int r0 = wm + mi * 16 + g;
        const float i0 = 1.f / (redsum[r0] + redsum[64 + r0] +
                                redsum[128 + r0] + redsum[192 + r0]);
        const float i1 = 1.f / (redsum[r0 + 8] + redsum[64 + r0 + 8] +
                                redsum[128 + r0 + 8] + redsum[192 + r0 + 8]);
#pragma unroll
        for (int ni = 0; ni < 8; ++ni) {
            const int cn = wn + ni * 8 + 2 * t;
            *(__half2*)&Ph[r0 * PP + cn] =
                __floats2half2_rn(accS[mi][ni][0] * i0, accS[mi][ni][1] * i0);
            *(__half2*)&Ph[(r0 + 8) * PP + cn] =
                __floats2half2_rn(accS[mi][ni][2] * i1, accS[mi][ni][3] * i1);
        }
    }
    __syncthreads();

    {
        const int wnO = (w & 3) * 16;
        float accO[2][2][4];
#pragma unroll
        for (int mi = 0; mi < 2; ++mi)
#pragma unroll
            for (int ni = 0; ni < 2; ++ni)
#pragma unroll
                for (int e2 = 0; e2 < 4; ++e2) accO[mi][ni][e2] = 0.f;

        const uint32_t p_tb = sbA + (uint32_t)(((wm + (l & 15)) * PP + ((l >> 4) << 3)) * 2);
        const uint32_t v_tb = sbA + ATT_V0 +
            (uint32_t)(((l & 15) * VP + wnO + ((l >> 4) << 3)) * 2);

#pragma unroll
        for (int kk = 0; kk < 16; ++kk) {
            uint32_t a[2][4];
#pragma unroll
            for (int mi = 0; mi < 2; ++mi)
                ldsm_x4(p_tb + (uint32_t)(mi * 16 * PP * 2 + kk * 32),
                        a[mi][0], a[mi][1], a[mi][2], a[mi][3]);
            uint32_t b00, b01, b10, b11;
            ldsm_x4_t(v_tb + (uint32_t)(kk * 16 * VP * 2), b00, b01, b10, b11);
#pragma unroll
            for (int mi = 0; mi < 2; ++mi) {
                mma_f16(accO[mi][0], a[mi][0], a[mi][1], a[mi][2], a[mi][3], b00, b01);
                mma_f16(accO[mi][1], a[mi][0], a[mi][1], a[mi][2], a[mi][3], b10, b11);
            }
        }
#pragma unroll
        for (int mi = 0; mi < 2; ++mi) {
            const int rr = wm + mi * 16 + g;
#pragma unroll
            for (int ni = 0; ni < 2; ++ni) {
                const int cn = wnO + ni * 8 + 2 * t;
                *(__half2*)&g_attnh[qbase + (size_t)rr * CC + cn] =
                    __floats2half2_rn(accO[mi][ni][0], accO[mi][ni][1]);
                *(__half2*)&g_attnh[qbase + (size_t)(rr + 8) * CC + cn] =
                    __floats2half2_rn(accO[mi][ni][2], accO[mi][ni][3]);
            }
        }
    }
}

// ---------------------------------------------------------------------------
extern "C" void kernel_launch(void* const* d_in, const int* in_sizes, int n_in,
                              void* d_out, int out_size)
{
    (void)in_sizes; (void)n_in; (void)out_size;
    const float* x     = (const float*)d_in[0];
    const float* wq    = (const float*)d_in[1];
    const float* bq    = (const float*)d_in[2];
    const float* wk    = (const float*)d_in[3];
    const float* bk    = (const float*)d_in[4];
    const float* wv    = (const float*)d_in[5];
    const float* bv    = (const float*)d_in[6];
    const float* w_sr  = (const float*)d_in[7];
    const float* b_sr  = (const float*)d_in[8];
    const float* gamma = (const float*)d_in[9];
    const float* beta  = (const float*)d_in[10];
    const float* wp    = (const float*)d_in[11];
    const float* bp    = (const float*)d_in[12];
    float* out = (float*)d_out;

    cudaFuncSetAttribute(conv_tc,    cudaFuncAttributeMaxDynamicSharedMemorySize, GEMM_SMEM);
    cudaFuncSetAttribute(qkv_tc,     cudaFuncAttributeMaxDynamicSharedMemorySize, GEMM_SMEM);
    cudaFuncSetAttribute(outproj_tc, cudaFuncAttributeMaxDynamicSharedMemorySize, GEMM_SMEM);
    cudaFuncSetAttribute(attn_kernel, cudaFuncAttributeMaxDynamicSharedMemorySize, ATT_SMEM);

    convert_all<<<6656, 256>>>(x, wq, wk, wv, wp, w_sr);
    conv_tc<<<512, 512, GEMM_SMEM>>>();
    ln_kernel<<<BB * NKV, 128>>>(b_sr, gamma, beta);
    qkv_tc<<<576, 512, GEMM_SMEM>>>(bq, bk, bv);
    attn_kernel<<<dim3(NQ / 64, BB * HEADS), 256, ATT_SMEM>>>();
    outproj_tc<<<512, 512, GEMM_SMEM>>>(bp, out);
}

// round 16
// speedup vs baseline: 1.3013x; 1.3013x over previous
#include <cuda_runtime.h>
#include <cuda_fp16.h>
#include <math.h>
#include <stdint.h>

#define BB    4
#define NQ    4096
#define CC    512
#define HEADS 8
#define DH    64
#define NKV   256
#define KCONV 8192
#define CSPLIT 16

// ---------------------------------------------------------------------------
// Scratch
// ---------------------------------------------------------------------------
__device__ __half g_xh[BB * NQ * CC];
__device__ __half g_qh[BB * NQ * CC];
__device__ __half g_kh[BB * NKV * CC];
__device__ __half g_vh[BB * NKV * CC];
__device__ __half g_attnh[BB * NQ * CC];
__device__ __half g_xrh[BB * NKV * CC];
__device__ __half g_xr_parth[CSPLIT * BB * NKV * CC];
__device__ __half g_wqh[CC * CC];
__device__ __half g_wkh[CC * CC];
__device__ __half g_wvh[CC * CC];
__device__ __half g_wph[CC * CC];
__device__ __half g_wsrh[(size_t)KCONV * CC];

// ---------------------------------------------------------------------------
// helpers
// ---------------------------------------------------------------------------
__device__ __forceinline__ void mma_f16(float* c,
    uint32_t a0, uint32_t a1, uint32_t a2, uint32_t a3, uint32_t b0, uint32_t b1)
{
    asm volatile(
        "mma.sync.aligned.m16n8k16.row.col.f32.f16.f16.f32 "
        "{%0,%1,%2,%3},{%4,%5,%6,%7},{%8,%9},{%0,%1,%2,%3};"
        : "+f"(c[0]), "+f"(c[1]), "+f"(c[2]), "+f"(c[3])
        : "r"(a0), "r"(a1), "r"(a2), "r"(a3), "r"(b0), "r"(b1));
}

__device__ __forceinline__ void ldsm_x4(uint32_t addr,
    uint32_t& r0, uint32_t& r1, uint32_t& r2, uint32_t& r3)
{
    asm volatile("ldmatrix.sync.aligned.m8n8.x4.shared.b16 {%0,%1,%2,%3}, [%4];"
        : "=r"(r0), "=r"(r1), "=r"(r2), "=r"(r3) : "r"(addr));
}

__device__ __forceinline__ void ldsm_x4_t(uint32_t addr,
    uint32_t& r0, uint32_t& r1, uint32_t& r2, uint32_t& r3)
{
    asm volatile("ldmatrix.sync.aligned.m8n8.x4.trans.shared.b16 {%0,%1,%2,%3}, [%4];"
        : "=r"(r0), "=r"(r1), "=r"(r2), "=r"(r3) : "r"(addr));
}

__device__ __forceinline__ uint32_t smem_u32(const void* p) {
    uint32_t a;
    asm("{ .reg .u64 t; cvta.to.shared.u64 t, %1; cvt.u32.u64 %0, t; }" : "=r"(a) : "l"(p));
    return a;
}

#define CP16(dst, src) \
    asm volatile("cp.async.cg.shared.global [%0], [%1], 16;" :: "r"(dst), "l"(src))
#define CPCOMMIT() asm volatile("cp.async.commit_group;" ::: "memory")

// ---------------------------------------------------------------------------
// fp16 GEMM core (R14 shape: 256 thr, 8 warps, warp tile 64x32) with explicit
// fragment double-buffering across the kk loop.
// ---------------------------------------------------------------------------
#define NSTAGE 3
#define AP   72
#define BP2  136
#define A_BYTES (128 * AP * 2)
#define B_OFF   A_BYTES
#define STAGE_BYTES (A_BYTES + 64 * BP2 * 2)
#define GEMM_SMEM (NSTAGE * STAGE_BYTES + 512)

template<bool OUTHALF, bool BIAS>
__device__ __forceinline__ void gemm_core(
    const __half* __restrict__ arow,   // per-thread A row base (row = tid>>1)
    const __half* __restrict__ Bk,
    const float* __restrict__ bias,
    void* __restrict__ Cp, int ldc,
    int nkt, int bm, int bn)
{
    extern __shared__ __align__(16) char smem[];
    float* sbias = (float*)(smem + NSTAGE * STAGE_BYTES);

    const int tid = threadIdx.x;
    const int w = tid >> 5, l = tid & 31;
    const int g = l >> 2, t = l & 3;
    const int wm = (w >> 2) * 64;
    const int wn = (w & 3) * 32;

    if (BIAS && tid < 128) sbias[tid] = bias[bn + tid];

    const int segA = (tid & 1) * 32;
    const int bK = tid >> 2;
    const int bN = (tid & 3) * 32;
    const uint32_t sb = smem_u32(smem);
    const uint32_t a_tb = (uint32_t)(((wm + (l & 15)) * AP + ((l >> 4) << 3)) * 2);
    const uint32_t b_tb = (uint32_t)(((l & 15) * BP2 + wn + ((l >> 4) << 3)) * 2);

    float acc[4][4][4];
#pragma unroll
    for (int mi = 0; mi < 4; ++mi)
#pragma unroll
        for (int ni = 0; ni < 4; ++ni)
#pragma unroll
            for (int e = 0; e < 4; ++e) acc[mi][ni][e] = 0.f;

#define ISSUE(ktArg, stArg) { \
    const uint32_t _ab = sb + (stArg) * STAGE_BYTES; \
    const __half* _ap = arow + (ktArg) * 64 + segA; \
    const uint32_t _ad = _ab + (uint32_t)((tid >> 1) * AP + segA) * 2; \
    CP16(_ad,      _ap);      CP16(_ad + 16, _ap + 8); \
    CP16(_ad + 32, _ap + 16); CP16(_ad + 48, _ap + 24); \
    const uint32_t _bb = _ab + B_OFF; \
    const __half* _bp = Bk + (size_t)((ktArg) * 64 + bK) * 512 + bn + bN; \
    const uint32_t _bd = _bb + (uint32_t)(bK * BP2 + bN) * 2; \
    CP16(_bd,      _bp);      CP16(_bd + 16, _bp + 8); \
    CP16(_bd + 32, _bp + 16); CP16(_bd + 48, _bp + 24); }

// load fragments for kkArg into slot sl
#define LDFRAG(kkArg, sl, abase, bbase) { \
    _Pragma("unroll") \
    for (int _mi = 0; _mi < 4; ++_mi) \
        ldsm_x4((abase) + a_tb + (uint32_t)(_mi * 16 * AP * 2 + (kkArg) * 32), \
                aF[sl][_mi][0], aF[sl][_mi][1], aF[sl][_mi][2], aF[sl][_mi][3]); \
    { \
        const uint32_t _bk0 = (bbase) + b_tb + (uint32_t)((kkArg) * 16 * BP2 * 2); \
        ldsm_x4_t(_bk0,      bF[sl][0][0], bF[sl][0][1], bF[sl][1][0], bF[sl][1][1]); \
        ldsm_x4_t(_bk0 + 32, bF[sl][2][0], bF[sl][2][1], bF[sl][3][0], bF[sl][3][1]); \
    } }

    ISSUE(0, 0); CPCOMMIT();
    if (nkt > 1) ISSUE(1, 1);
    CPCOMMIT();

    uint32_t aF[2][4][4], bF[2][4][2];

    int buf = 0, nxt = 2;
    for (int kt = 0; kt < nkt; ++kt) {
        asm volatile("cp.async.wait_group 1;" ::: "memory");
        __syncthreads();
        if (kt + 2 < nkt) ISSUE(kt + 2, nxt);
        CPCOMMIT();

        const uint32_t abase = sb + buf * STAGE_BYTES;
        const uint32_t bbase = abase + B_OFF;

        LDFRAG(0, 0, abase, bbase);
#pragma unroll
        for (int kk = 0; kk < 4; ++kk) {
            const int cur = kk & 1;
            if (kk < 3) LDFRAG(kk + 1, cur ^ 1, abase, bbase);
#pragma unroll
            for (int ni = 0; ni < 4; ++ni)
#pragma unroll
                for (int mi = 0; mi < 4; ++mi)
                    mma_f16(acc[mi][ni],
                            aF[cur][mi][0], aF[cur][mi][1], aF[cur][mi][2], aF[cur][mi][3],
                            bF[cur][ni][0], bF[cur][ni][1]);
        }
        buf = (buf == 2) ? 0 : buf + 1;
        nxt = (nxt == 2) ? 0 : nxt + 1;
    }
#undef ISSUE
#undef LDFRAG

    __syncthreads();

#pragma unroll
    for (int mi = 0; mi < 4; ++mi) {
        const int r0 = bm + wm + mi * 16 + g;
#pragma unroll
        for (int ni = 0; ni < 4; ++ni) {
            const int cl = wn + ni * 8 + 2 * t;
            const int cn = bn + cl;
            float f0 = acc[mi][ni][0], f1 = acc[mi][ni][1];
            float f2 = acc[mi][ni][2], f3 = acc[mi][ni][3];
            if (BIAS) {
                const float b0 = sbias[cl], b1 = sbias[cl + 1];
                f0 += b0; f1 += b1; f2 += b0; f3 += b1;
            }
            if (OUTHALF) {
                __half* C = (__half*)Cp;
                *(__half2*)&C[(size_t)r0 * ldc + cn] = __floats2half2_rn(f0, f1);
                *(__half2*)&C[(size_t)(r0 + 8) * ldc + cn] = __floats2half2_rn(f2, f3);
            } else {
                float* C = (float*)Cp;
                *(float2*)&C[(size_t)r0 * ldc + cn] = make_float2(f0, f1);
                *(float2*)&C[(size_t)(r0 + 8) * ldc + cn] = make_float2(f2, f3);
            }
        }
    }
}

// ---------------------------------------------------------------------------
// conv-only kernel: grid 512, fp16 partials
// ---------------------------------------------------------------------------
__global__ void __launch_bounds__(256, 2) conv_tc()
{
    const int c = blockIdx.x;
    const int r = threadIdx.x >> 1;
    const int z = c >> 5, tl = c & 31;
    const int bm = (tl >> 2) * 128, bn = (tl & 3) * 128;
    const int gr = bm + r;
    const int pix = (gr >> 8) * 4096 + (((gr >> 4) & 15) << 8) + ((gr & 15) << 2);
    const int off = ((z >> 2) << 6) | (z & 3);
    const __half* arow = g_xh + (size_t)(pix + off) * 512;
    gemm_core<true, false>(arow, g_wsrh + (size_t)z * 512 * 512, nullptr,
                           g_xr_parth + (size_t)z * (BB * NKV * CC), 512, 8, bm, bn);
}

// ---------------------------------------------------------------------------
// merged qproj + K + V kernel: grid 576
// ---------------------------------------------------------------------------
__global__ void __launch_bounds__(256, 2) qkv_tc(const float* __restrict__ bq,
                                                 const float* __restrict__ bk,
                                                 const float* __restrict__ bv)
{
    const int bid = blockIdx.x;
    const int r = threadIdx.x >> 1;
    if (bid < 512) {
        const int bm = (bid >> 2) * 128, bn = (bid & 3) * 128;
        const __half* arow = g_xh + (size_t)(bm + r) * 512;
        gemm_core<true, true>(arow, g_wqh, bq, g_qh, 512, 8, bm, bn);
    } else {
        const int tl = bid - 512;
        const int sel = tl >> 5;
        const int tt = tl & 31;
        const int bm = (tt >> 2) * 128, bn = (tt & 3) * 128;
        const __half* arow = g_xrh + (size_t)(bm + r) * 512;
        if (sel == 0)
            gemm_core<true, true>(arow, g_wkh, bk, g_kh, 512, 8, bm, bn);
        else
            gemm_core<true, true>(arow, g_wvh, bv, g_vh, 512, 8, bm, bn);
    }
}

__global__ void __launch_bounds__(256, 2) outproj_tc(const float* __restrict__ bp,
                                                     float* __restrict__ out)
{
    const int bid = blockIdx.x;
    const int bm = (bid >> 2) * 128, bn = (bid & 3) * 128;
    const __half* arow = g_attnh + (size_t)(bm + (threadIdx.x >> 1)) * 512;
    gemm_core<false, true>(arow, g_wph, bp, out, 512, 8, bm, bn);
}

// ---------------------------------------------------------------------------
// Convert x + all weights to fp16
// ---------------------------------------------------------------------------
__global__ void convert_all(const float* __restrict__ x,
                            const float* __restrict__ wq,
                            const float* __restrict__ wk,
                            const float* __restrict__ wv,
                            const float* __restrict__ wp,
                            const float* __restrict__ w_sr)
{
    const size_t cid = (size_t)blockIdx.x * blockDim.x + threadIdx.x;
    const float* src;
    __half* dst;
    size_t loc;
    if (cid < 1048576)        { src = x;    dst = g_xh;  loc = cid; }
    else if (cid < 1081344)   { src = wq;   dst = g_wqh; loc = cid - 1048576; }
    else if (cid < 1114112)   { src = wk;   dst = g_wkh; loc = cid - 1081344; }
    else if (cid < 1146880)   { src = wv;   dst = g_wvh; loc = cid - 1114112; }
    else if (cid < 1179648)   { src = wp;   dst = g_wph; loc = cid - 1146880; }
    else                      { src = w_sr; dst = g_wsrh; loc = cid - 1179648; }
    const size_t i = loc * 8;
    float4 u = *(const float4*)&src[i];
    float4 v = *(const float4*)&src[i + 4];
    __half2 h0 = __floats2half2_rn(u.x, u.y);
    __half2 h1 = __floats2half2_rn(u.z, u.w);
    __half2 h2 = __floats2half2_rn(v.x, v.y);
    __half2 h3 = __floats2half2_rn(v.z, v.w);
    uint4 pk;
    pk.x = *(uint32_t*)&h0; pk.y = *(uint32_t*)&h1;
    pk.z = *(uint32_t*)&h2; pk.w = *(uint32_t*)&h3;
    *(uint4*)&dst[i] = pk;
}

// ---------------------------------------------------------------------------
// split-K reduce (fp16 partials) + bias + LayerNorm -> fp16
// ---------------------------------------------------------------------------
__global__ void ln_kernel(const float* __restrict__ bsr,
                          const float* __restrict__ gamma,
                          const float* __restrict__ beta)
{
    const int r = blockIdx.x;
    const int tid = threadIdx.x;
    float v[4];
    float s1 = 0.f, s2 = 0.f;
#pragma unroll
    for (int i = 0; i < 4; ++i) {
        const int c = tid + i * 128;
        const size_t off = (size_t)r * 512 + c;
        float tt = bsr[c];
#pragma unroll
        for (int p = 0; p < CSPLIT; ++p)
            tt += __half2float(g_xr_parth[(size_t)p * (BB * NKV * CC) + off]);
        v[i] = tt;
        s1 += tt;
        s2 += tt * tt;
    }
#pragma unroll
    for (int o = 16; o > 0; o >>= 1) {
        s1 += __shfl_xor_sync(0xffffffffu, s1, o);
        s2 += __shfl_xor_sync(0xffffffffu, s2, o);
    }
    __shared__ float red[8];
    const int warp = tid >> 5, lane = tid & 31;
    if (lane == 0) { red[warp] = s1; red[warp + 4] = s2; }
    __syncthreads();
    s1 = red[0] + red[1] + red[2] + red[3];
    s2 = red[4] + red[5] + red[6] + red[7];
    const float mu = s1 * (1.f / 512.f);
    const float var = s2 * (1.f / 512.f) - mu * mu;
    const float rstd = rsqrtf(var + 1e-5f);
#pragma unroll
    for (int i = 0; i < 4; ++i) {
        const int c = tid + i * 128;
        g_xrh[(size_t)r * 512 + c] = __float2half((v[i] - mu) * rstd * gamma[c] + beta[c]);
    }
}

// ---------------------------------------------------------------------------
// Attention v3 (byte-identical to passing R14)
// ---------------------------------------------------------------------------
#define QP 72
#define KP 72
#define VP 72
#define PP 280
#define ATT_K0 9216
#define ATT_V0 46080
#define ATT_RM 82944
#define ATT_RS 83968
#define ATT_SMEM 84992

__global__ void __launch_bounds__(256, 2) attn_kernel()
{
    extern __shared__ __align__(16) char smem[];
    __half* Ph = (__half*)smem;
    float* redmax = (float*)(smem + ATT_RM);
    float* redsum = (float*)(smem + ATT_RS);

    const int tid = threadIdx.x;
    const int w = tid >> 5, l = tid & 31;
    const int g = l >> 2, t = l & 3;
    const uint32_t sbA = smem_u32(smem);

    const int bh = blockIdx.y;
    const int b = bh >> 3, h = bh & 7;
    const int q0 = blockIdx.x * 64;
    const size_t qbase  = ((size_t)(b * NQ + q0)) * CC + h * DH;
    const size_t kvbase = ((size_t)(b * NKV)) * CC + h * DH;

#pragma unroll
    for (int i = 0; i < 2; ++i) {
        const int c = tid + i * 256;
        const int r = c >> 3, seg = (c & 7) * 8;
        CP16(sbA + (uint32_t)(r * QP + seg) * 2, &g_qh[qbase + (size_t)r * CC + seg]);
    }
#pragma unroll
    for (int i = 0; i < 8; ++i) {
        const int c = tid + i * 256;
        const int r = c >> 3, seg = (c & 7) * 8;
        CP16(sbA + ATT_K0 + (uint32_t)(r * KP + seg) * 2, &g_kh[kvbase + (size_t)r * CC + seg]);
    }
    CPCOMMIT();
#pragma unroll
    for (int i = 0; i < 8; ++i) {
        const int c = tid + i * 256;
        const int r = c >> 3, seg = (c & 7) * 8;
        CP16(sbA + ATT_V0 + (uint32_t)(r * VP + seg) * 2, &g_vh[kvbase + (size_t)r * CC + seg]);
    }
    CPCOMMIT();
    asm volatile("cp.async.wait_group 1;" ::: "memory");
    __syncthreads();

    const int wm = (w >> 2) * 32;
    const int wn = (w & 3) * 64;

    const uint32_t q_tb = sbA + (uint32_t)(((wm + (l & 15)) * QP + ((l >> 4) << 3)) * 2);
    const uint32_t k_tb = sbA + ATT_K0 + (uint32_t)(((wn + (l & 15)) * KP + ((l >> 4) << 3)) * 2);

    float accS[2][8][4];
#pragma unroll
    for (int mi = 0; mi < 2; ++mi)
#pragma unroll
        for (int ni = 0; ni < 8; ++ni)
#pragma unroll
            for (int e = 0; e < 4; ++e) accS[mi][ni][e] = 0.f;

#pragma unroll
    for (int kk = 0; kk < 4; ++kk) {
        uint32_t a[2][4];
#pragma unroll
        for (int mi = 0; mi < 2; ++mi)
            ldsm_x4(q_tb + (uint32_t)(mi * 16 * QP * 2 + kk * 32),
                    a[mi][0], a[mi][1], a[mi][2], a[mi][3]);
#pragma unroll
        for (int j = 0; j < 4; ++j) {
            uint32_t r0, r1, r2, r3;
            ldsm_x4(k_tb + (uint32_t)(j * 16 * KP * 2 + kk * 32), r0, r1, r2, r3);
#pragma unroll
            for (int mi = 0; mi < 2; ++mi) {
                mma_f16(accS[mi][2 * j],     a[mi][0], a[mi][1], a[mi][2], a[mi][3], r0, r2);
                mma_f16(accS[mi][2 * j + 1], a[mi][0], a[mi][1], a[mi][2], a[mi][3], r1, r3);
            }
        }
    }
#pragma unroll
    for (int mi = 0; mi < 2; ++mi)
#pragma unroll
        for (int ni = 0; ni < 8; ++ni)
#pragma unroll
            for (int e = 0; e < 4; ++e) accS[mi][ni][e] *= 0.125f;

#pragma unroll
    for (int mi = 0; mi < 2; ++mi) {
        float m0 = -1e30f, m1 = -1e30f;
#pragma unroll
        for (int ni = 0; ni < 8; ++ni) {
            m0 = fmaxf(m0, fmaxf(accS[mi][ni][0], accS[mi][ni][1]));
            m1 = fmaxf(m1, fmaxf(accS[mi][ni][2], accS[mi][ni][3]));
        }
        m0 = fmaxf(m0, __shfl_xor_sync(0xffffffffu, m0, 1));
        m0 = fmaxf(m0, __shfl_xor_sync(0xffffffffu, m0, 2));
        m1 = fmaxf(m1, __shfl_xor_sync(0xffffffffu, m1, 1));
        m1 = fmaxf(m1, __shfl_xor_sync(0xffffffffu, m1, 2));
        if (t == 0) {
            redmax[(w & 3) * 64 + wm + mi * 16 + g]     = m0;
            redmax[(w & 3) * 64 + wm + mi * 16 + g + 8] = m1;
        }
    }
    __syncthreads();

#pragma unroll
    for (int mi = 0; mi < 2; ++mi) {
        const int r0 = wm + mi * 16 + g;
        const float m0 = fmaxf(fmaxf(redmax[r0], redmax[64 + r0]),
                               fmaxf(redmax[128 + r0], redmax[192 + r0]));
        const float m1 = fmaxf(fmaxf(redmax[r0 + 8], redmax[64 + r0 + 8]),
                               fmaxf(redmax[128 + r0 + 8], redmax[192 + r0 + 8]));
        float s0 = 0.f, s1 = 0.f;
#pragma unroll
        for (int ni = 0; ni < 8; ++ni) {
            accS[mi][ni][0] = __expf(accS[mi][ni][0] - m0);
            accS[mi][ni][1] = __expf(accS[mi][ni][1] - m0);
            accS[mi][ni][2] = __expf(accS[mi][ni][2] - m1);
            accS[mi][ni][3] = __expf(accS[mi][ni][3] - m1);
            s0 += accS[mi][ni][0] + accS[mi][ni][1];
            s1 += accS[mi][ni][2] + accS[mi][ni][3];
        }
        s0 += __shfl_xor_sync(0xffffffffu, s0, 1);
        s0 += __shfl_xor_sync(0xffffffffu, s0, 2);
        s1 += __shfl_xor_sync(0xffffffffu, s1, 1);
        s1 += __shfl_xor_sync(0xffffffffu, s1, 2);
        if (t == 0) {
            redsum[(w & 3) * 64 + r0]     = s0;
            redsum[(w & 3) * 64 + r0 + 8] = s1;
        }
    }
    asm volatile("cp.async.wait_group 0;" ::: "memory");
    __syncthreads();

#pragma unroll
    for (int mi = 0; mi < 2; ++mi) {
        const int r0 = wm + mi * 16 + g;
        const float i0 = 1.f / (redsum[r0] + redsum[64 + r0] +
                                redsum[128 + r0] + redsum[192 + r0]);
        const float i1 = 1.f / (redsum[r0 + 8] + redsum[64 + r0 + 8] +
                                redsum[128 + r0 + 8] + redsum[192 + r0 + 8]);
#pragma unroll
        for (int ni = 0; ni < 8; ++ni) {
            const int cn = wn + ni * 8 + 2 * t;
            *(__half2*)&Ph[r0 * PP + cn] =
                __floats2half2_rn(accS[mi][ni][0] * i0, accS[mi][ni][1] * i0);
            *(__half2*)&Ph[(r0 + 8) * PP + cn] =
                __floats2half2_rn(accS[mi][ni][2] * i1, accS[mi][ni][3] * i1);
        }
    }
    __syncthreads();

    {
        const int wnO = (w & 3) * 16;
        float accO[2][2][4];
#pragma unroll
        for (int mi = 0; mi < 2; ++mi)
#pragma unroll
            for (int ni = 0; ni < 2; ++ni)
#pragma unroll
                for (int e2 = 0; e2 < 4; ++e2) accO[mi][ni][e2] = 0.f;

        const uint32_t p_tb = sbA + (uint32_t)(((wm + (l & 15)) * PP + ((l >> 4) << 3)) * 2);
        const uint32_t v_tb = sbA + ATT_V0 +
            (uint32_t)(((l & 15) * VP + wnO + ((l >> 4) << 3)) * 2);

#pragma unroll
        for (int kk = 0; kk < 16; ++kk) {
            uint32_t a[2][4];
#pragma unroll
            for (int mi = 0; mi < 2; ++mi)
                ldsm_x4(p_tb + (uint32_t)(mi * 16 * PP * 2 + kk * 32),
                        a[mi][0], a[mi][1], a[mi][2], a[mi][3]);
            uint32_t b00, b01, b10, b11;
            ldsm_x4_t(v_tb + (uint32_t)(kk * 16 * VP * 2), b00, b01, b10, b11);
#pragma unroll
            for (int mi = 0; mi < 2; ++mi) {
                mma_f16(accO[mi][0], a[mi][0], a[mi][1], a[mi][2], a[mi][3], b00, b01);
                mma_f16(accO[mi][1], a[mi][0], a[mi][1], a[mi][2], a[mi][3], b10, b11);
            }
        }
#pragma unroll
        for (int mi = 0; mi < 2; ++mi) {
            const int rr = wm + mi * 16 + g;
#pragma unroll
            for (int ni = 0; ni < 2; ++ni) {
                const int cn = wnO + ni * 8 + 2 * t;
                *(__half2*)&g_attnh[qbase + (size_t)rr * CC + cn] =
                    __floats2half2_rn(accO[mi][ni][0], accO[mi][ni][1]);
                *(__half2*)&g_attnh[qbase + (size_t)(rr + 8) * CC + cn] =
                    __floats2half2_rn(accO[mi][ni][2], accO[mi][ni][3]);
            }
        }
    }
}

// ---------------------------------------------------------------------------
extern "C" void kernel_launch(void* const* d_in, const int* in_sizes, int n_in,
                              void* d_out, int out_size)
{
    (void)in_sizes; (void)n_in; (void)out_size;
    const float* x     = (const float*)d_in[0];
    const float* wq    = (const float*)d_in[1];
    const float* bq    = (const float*)d_in[2];
    const float* wk    = (const float*)d_in[3];
    const float* bk    = (const float*)d_in[4];
    const float* wv    = (const float*)d_in[5];
    const float* bv    = (const float*)d_in[6];
    const float* w_sr  = (const float*)d_in[7];
    const float* b_sr  = (const float*)d_in[8];
    const float* gamma = (const float*)d_in[9];
    const float* beta  = (const float*)d_in[10];
    const float* wp    = (const float*)d_in[11];
    const float* bp    = (const float*)d_in[12];
    float* out = (float*)d_out;

    cudaFuncSetAttribute(conv_tc,    cudaFuncAttributeMaxDynamicSharedMemorySize, GEMM_SMEM);
    cudaFuncSetAttribute(qkv_tc,     cudaFuncAttributeMaxDynamicSharedMemorySize, GEMM_SMEM);
    cudaFuncSetAttribute(outproj_tc, cudaFuncAttributeMaxDynamicSharedMemorySize, GEMM_SMEM);
    cudaFuncSetAttribute(attn_kernel, cudaFuncAttributeMaxDynamicSharedMemorySize, ATT_SMEM);

    convert_all<<<6656, 256>>>(x, wq, wk, wv, wp, w_sr);
    conv_tc<<<512, 256, GEMM_SMEM>>>();
    ln_kernel<<<BB * NKV, 128>>>(b_sr, gamma, beta);
    qkv_tc<<<576, 256, GEMM_SMEM>>>(bq, bk, bv);
    attn_kernel<<<dim3(NQ / 64, BB * HEADS), 256, ATT_SMEM>>>();
    outproj_tc<<<512, 256, GEMM_SMEM>>>(bp, out);
}